// round 6
// baseline (speedup 1.0000x reference)
#include <cuda_runtime.h>

#define NMAX 100000
#define EMAX 1600000
#define HID 64
#define SCAN_CHUNK 1024   // elements per scan block (256 thr * 4)

typedef unsigned long long u64;

// scratch (no cudaMalloc allowed)
__device__ __align__(16) float g_xp [NMAX * HID];
__device__ __align__(16) float g_h  [NMAX * HID];
__device__ float g_als[NMAX * 2];
__device__ float g_ald[NMAX * 2];
__device__ int   g_cnt[NMAX];
__device__ int   g_off[NMAX + 1];
__device__ int   g_cur[NMAX];
__device__ int   g_srcs[EMAX];
__device__ int   g_bsums[(NMAX + SCAN_CHUNK - 1) / SCAN_CHUNK];
__device__ int   g_boff [(NMAX + SCAN_CHUNK - 1) / SCAN_CHUNK];
__device__ int   g_is64;

// ---------------------------------------------------------------------------
// packed f32x2 helpers (FFMA2 — ptxas never auto-fuses; PTX-only)
// ---------------------------------------------------------------------------
__device__ __forceinline__ void ffma2(u64 &acc, u64 a, u64 b)
{
    asm("fma.rn.f32x2 %0, %1, %2, %0;" : "+l"(acc) : "l"(a), "l"(b));
}
__device__ __forceinline__ u64 pack_dup(float x)
{
    u64 d; asm("mov.b64 %0, {%1, %1};" : "=l"(d) : "f"(x)); return d;
}
__device__ __forceinline__ float2 unpack2(u64 d)
{
    float2 f; asm("mov.b64 {%0, %1}, %2;" : "=f"(f.x), "=f"(f.y) : "l"(d));
    return f;
}

// ---------------------------------------------------------------------------
// Detect whether edge_index is stored as int64 (high 32-bit words all zero)
// or int32. Checks the first 2048 odd words.
// ---------------------------------------------------------------------------
__global__ __launch_bounds__(256)
void detect_kernel(const int* __restrict__ ei)
{
    __shared__ int s_or;
    if (threadIdx.x == 0) s_or = 0;
    __syncthreads();
    int o = 0;
    for (int i = threadIdx.x; i < 2048; i += 256)
        o |= ei[2 * i + 1];
    if (o) atomicOr(&s_or, 1);
    __syncthreads();
    if (threadIdx.x == 0) g_is64 = (s_or == 0) ? 1 : 0;
}

__device__ __forceinline__ int load_src(const int* ei, int E, int i, int is64)
{
    return is64 ? ei[2 * i] : ei[i];
}
__device__ __forceinline__ int load_dst(const int* ei, int E, int i, int is64)
{
    return is64 ? ei[2 * E + 2 * i] : ei[E + i];
}

// ---------------------------------------------------------------------------
// CSR build (by destination). Only integer atomics.
// ---------------------------------------------------------------------------
__global__ __launch_bounds__(256)
void zero_cnt_kernel(int n)
{
    int i = blockIdx.x * blockDim.x + threadIdx.x;
    if (i < n) g_cnt[i] = 0;
}

__global__ __launch_bounds__(256)
void hist_kernel(const int* __restrict__ ei, int E)
{
    int i = blockIdx.x * blockDim.x + threadIdx.x;
    int is64 = g_is64;
    if (i < E) atomicAdd(&g_cnt[load_dst(ei, E, i, is64)], 1);
}

// ---------------------------------------------------------------------------
// 3-phase parallel exclusive scan over g_cnt[0..n) -> g_off/g_cur, g_off[n]=E
// ---------------------------------------------------------------------------
__device__ __forceinline__ int block_exscan256(int v, int* sh)
{
    const int t = threadIdx.x;
    sh[t] = v;
    __syncthreads();
#pragma unroll
    for (int off = 1; off < 256; off <<= 1) {
        int u = (t >= off) ? sh[t - off] : 0;
        __syncthreads();
        sh[t] += u;
        __syncthreads();
    }
    return sh[t] - v;
}

__global__ __launch_bounds__(256)
void scan_partial(int n)
{
    __shared__ int sh[256];
    const int t = threadIdx.x;
    const int base = blockIdx.x * SCAN_CHUNK + t * 4;
    int s = 0;
#pragma unroll
    for (int j = 0; j < 4; j++)
        if (base + j < n) s += g_cnt[base + j];
    sh[t] = s;
    __syncthreads();
    for (int off = 128; off; off >>= 1) {
        if (t < off) sh[t] += sh[t + off];
        __syncthreads();
    }
    if (t == 0) g_bsums[blockIdx.x] = sh[0];
}

__global__ __launch_bounds__(256)
void scan_bsums(int nb)
{
    __shared__ int sh[256];
    const int t = threadIdx.x;
    int v = (t < nb) ? g_bsums[t] : 0;
    int ex = block_exscan256(v, sh);
    if (t < nb) g_boff[t] = ex;
}

__global__ __launch_bounds__(256)
void scan_final(int n, int E)
{
    __shared__ int sh[256];
    const int t = threadIdx.x;
    const int base = blockIdx.x * SCAN_CHUNK + t * 4;
    int c[4];
    int s = 0;
#pragma unroll
    for (int j = 0; j < 4; j++) {
        c[j] = (base + j < n) ? g_cnt[base + j] : 0;
        s += c[j];
    }
    int ex = block_exscan256(s, sh) + g_boff[blockIdx.x];
#pragma unroll
    for (int j = 0; j < 4; j++) {
        if (base + j < n) {
            g_off[base + j] = ex;
            g_cur[base + j] = ex;
        }
        ex += c[j];
    }
    if (blockIdx.x == 0 && t == 0) g_off[n] = E;
}

__global__ __launch_bounds__(256)
void scatter_kernel(const int* __restrict__ ei, int E)
{
    int i = blockIdx.x * blockDim.x + threadIdx.x;
    if (i >= E) return;
    int is64 = g_is64;
    int d = load_dst(ei, E, i, is64);
    int s = load_src(ei, E, i, is64);
    int pos = atomicAdd(&g_cur[d], 1);
    g_srcs[pos] = s;
}

// ---------------------------------------------------------------------------
// Fused GEMM + attention-logit epilogue, FFMA2-packed.
//   xp = X @ W  (X:[n,K], W:[K,64])  -> g_xp
//   al_src[n,h] = <xp[n,h,:], att_s[h,:]>  -> g_als ; al_dst -> g_ald
// Block: 256 thr, tile 128 rows x 64 cols, thread tile 4 rows x 8 cols
// (4 packed col-pairs), K chunked by 64.
// ---------------------------------------------------------------------------
template<int K, bool FIRST>
__global__ __launch_bounds__(256)
void gemm_al_kernel(const float* __restrict__ Xin,
                    const float* __restrict__ W,
                    const float* __restrict__ att_s,
                    const float* __restrict__ att_d,
                    int n)
{
    const float* __restrict__ X = FIRST ? Xin : g_h;

    __shared__ __align__(16) float sW[64 * 64];
    __shared__ __align__(16) float sXT[64][129];   // k-major, 128 rows + pad

    const int tid = threadIdx.x;
    const int cx  = tid & 7;            // col group: 8 cols (4 packed pairs)
    const int ry  = tid >> 3;           // row group: 4 rows
    const int row0 = blockIdx.x * 128;

    u64 C2[4][4];
#pragma unroll
    for (int i = 0; i < 4; i++)
#pragma unroll
        for (int jp = 0; jp < 4; jp++) C2[i][jp] = 0ull;

    for (int kc = 0; kc < K; kc += 64) {
        __syncthreads();
        // load W chunk: 64x64 floats
#pragma unroll
        for (int q = 0; q < 4; q++) {
            int idx4 = tid + q * 256;
            float4 v = *(const float4*)&W[kc * 64 + idx4 * 4];
            *(float4*)&sW[idx4 * 4] = v;
        }
        // load X tile transposed: 128 rows x 64 k
#pragma unroll
        for (int q = 0; q < 8; q++) {
            int lin = tid + q * 256;
            int r  = lin >> 4;
            int c4 = lin & 15;
            int gr = row0 + r; if (gr > n - 1) gr = n - 1;
            float4 v = *(const float4*)&X[(long long)gr * K + kc + c4 * 4];
            sXT[c4 * 4 + 0][r] = v.x;
            sXT[c4 * 4 + 1][r] = v.y;
            sXT[c4 * 4 + 2][r] = v.z;
            sXT[c4 * 4 + 3][r] = v.w;
        }
        __syncthreads();
#pragma unroll
        for (int k = 0; k < 64; k++) {
            // 8 cols = 4 packed pairs, loaded directly as u64s (no MOVs)
            ulonglong2 wa = *(const ulonglong2*)&sW[k * 64 + cx * 8];
            ulonglong2 wb = *(const ulonglong2*)&sW[k * 64 + cx * 8 + 4];
#pragma unroll
            for (int i = 0; i < 4; i++) {
                u64 xx = pack_dup(sXT[k][ry * 4 + i]);
                ffma2(C2[i][0], xx, wa.x);
                ffma2(C2[i][1], xx, wa.y);
                ffma2(C2[i][2], xx, wb.x);
                ffma2(C2[i][3], xx, wb.y);
            }
        }
    }

    // unpack accumulators
    float C[4][8];
#pragma unroll
    for (int i = 0; i < 4; i++)
#pragma unroll
        for (int jp = 0; jp < 4; jp++) {
            float2 f = unpack2(C2[i][jp]);
            C[i][jp * 2 + 0] = f.x;
            C[i][jp * 2 + 1] = f.y;
        }

    // epilogue: attention logits (this thread's 8 cols lie within one head)
    const int h    = cx >> 2;           // cx 0-3 -> head 0, 4-7 -> head 1
    const int lane = tid & 31;
    float asv[8], adv[8];
#pragma unroll
    for (int j = 0; j < 8; j++) {
        asv[j] = __ldg(&att_s[cx * 8 + j]);
        adv[j] = __ldg(&att_d[cx * 8 + j]);
    }

#pragma unroll
    for (int i = 0; i < 4; i++) {
        float als = 0.f, ald = 0.f;
#pragma unroll
        for (int j = 0; j < 8; j++) {
            als = fmaf(C[i][j], asv[j], als);
            ald = fmaf(C[i][j], adv[j], ald);
        }
        // reduce across the 4-lane col group (aligned 4-lane segments)
        als += __shfl_down_sync(0xffffffffu, als, 2, 4);
        ald += __shfl_down_sync(0xffffffffu, ald, 2, 4);
        als += __shfl_down_sync(0xffffffffu, als, 1, 4);
        ald += __shfl_down_sync(0xffffffffu, ald, 1, 4);

        int row = row0 + ry * 4 + i;
        if (row < n) {
            if ((lane & 3) == 0) {
                g_als[row * 2 + h] = als;
                g_ald[row * 2 + h] = ald;
            }
            *(float4*)&g_xp[row * HID + cx * 8]     =
                make_float4(C[i][0], C[i][1], C[i][2], C[i][3]);
            *(float4*)&g_xp[row * HID + cx * 8 + 4] =
                make_float4(C[i][4], C[i][5], C[i][6], C[i][7]);
        }
    }
}

// ---------------------------------------------------------------------------
// Gather pass: one warp per destination node. No float atomics.
//   w_e = exp(lrelu(als[s]+ald[d])) ; acc += xp[s]*w ; seg += w
// Self-loop folded into init. Finish: acc/seg + bias (+ELU for layer 1).
// ---------------------------------------------------------------------------
template<bool LAST>
__global__ __launch_bounds__(256)
void gather_kernel(const float* __restrict__ bias,
                   float* __restrict__ out, int n)
{
    int warp = (blockIdx.x * 256 + threadIdx.x) >> 5;
    int lane = threadIdx.x & 31;
    if (warp >= n) return;
    const int node = warp;
    const int h = lane >> 4;            // lanes 0-15: head 0, 16-31: head 1

    const float ald_h = __ldg(&g_ald[node * 2 + h]);

    // self loop
    float t0 = __ldg(&g_als[node * 2 + h]) + ald_h;
    t0 = fmaxf(t0, 0.2f * t0);
    float w = __expf(t0);
    float2 xv = *(const float2*)&g_xp[node * HID + lane * 2];
    float a0 = xv.x * w, a1 = xv.y * w, seg = w;

    const int beg = g_off[node];
    const int end = g_off[node + 1];
    for (int i = beg; i < end; i += 32) {
        int cnt = min(32, end - i);
        int sidx = (i + lane < end) ? __ldg(&g_srcs[i + lane]) : 0;
#pragma unroll 4
        for (int j = 0; j < cnt; j++) {
            int s = __shfl_sync(0xffffffffu, sidx, j);
            float tt = __ldg(&g_als[s * 2 + h]) + ald_h;
            tt = fmaxf(tt, 0.2f * tt);
            float ww = __expf(tt);
            float2 xs = *(const float2*)&g_xp[s * HID + lane * 2];
            a0 = fmaf(xs.x, ww, a0);
            a1 = fmaf(xs.y, ww, a1);
            seg += ww;
        }
    }

    float inv = 1.f / (seg + 1e-16f);
    float2 bv = *(const float2*)&bias[lane * 2];
    float v0 = a0 * inv + bv.x;
    float v1 = a1 * inv + bv.y;
    if (!LAST) {
        v0 = v0 > 0.f ? v0 : expm1f(v0);
        v1 = v1 > 0.f ? v1 : expm1f(v1);
        *(float2*)&g_h[node * HID + lane * 2] = make_float2(v0, v1);
    } else {
        *(float2*)&out[node * HID + lane * 2] = make_float2(v0, v1);
    }
}

extern "C" void kernel_launch(void* const* d_in, const int* in_sizes, int n_in,
                              void* d_out, int out_size)
{
    const float* x   = (const float*)d_in[0];
    const int*   ei  = (const int*)d_in[1];
    const float* W1  = (const float*)d_in[2];
    const float* as1 = (const float*)d_in[3];
    const float* ad1 = (const float*)d_in[4];
    const float* b1  = (const float*)d_in[5];
    const float* W2  = (const float*)d_in[6];
    const float* as2 = (const float*)d_in[7];
    const float* ad2 = (const float*)d_in[8];
    const float* b2  = (const float*)d_in[9];

    const int n = in_sizes[0] / 128;          // 100000
    const int E = in_sizes[1] / 2;            // 1600000
    const int gb  = (n + 127) / 128;
    const int nbl = (n + 255) / 256;
    const int ebl = (E + 255) / 256;
    const int wbl = ((n * 32) + 255) / 256;   // warp per node
    const int sb  = (n + SCAN_CHUNK - 1) / SCAN_CHUNK;

    // CSR build (graph is shared by both layers)
    detect_kernel<<<1, 256>>>(ei);
    zero_cnt_kernel<<<nbl, 256>>>(n);
    hist_kernel<<<ebl, 256>>>(ei, E);
    scan_partial<<<sb, 256>>>(n);
    scan_bsums<<<1, 256>>>(sb);
    scan_final<<<sb, 256>>>(n, E);
    scatter_kernel<<<ebl, 256>>>(ei, E);

    // layer 1
    gemm_al_kernel<128, true><<<gb, 256>>>(x, W1, as1, ad1, n);
    gather_kernel<false><<<wbl, 256>>>(b1, nullptr, n);
    // layer 2
    gemm_al_kernel<64, false><<<gb, 256>>>(x, W2, as2, ad2, n);
    gather_kernel<true><<<wbl, 256>>>(b2, (float*)d_out, n);
}

// round 7
// speedup vs baseline: 1.1243x; 1.1243x over previous
#include <cuda_runtime.h>

#define NMAX 100000
#define EMAX 1600000
#define HID 64
#define SCAN_CHUNK 1024   // elements per scan block (256 thr * 4)

// scratch (no cudaMalloc allowed)
__device__ __align__(16) float g_xp [NMAX * HID];
__device__ __align__(16) float g_h  [NMAX * HID];
__device__ float g_als[NMAX * 2];
__device__ float g_ald[NMAX * 2];
__device__ int   g_cnt[NMAX];
__device__ int   g_off[NMAX + 1];
__device__ int   g_cur[NMAX];
__device__ int   g_srcs[EMAX];
__device__ int   g_bsums[(NMAX + SCAN_CHUNK - 1) / SCAN_CHUNK];
__device__ int   g_boff [(NMAX + SCAN_CHUNK - 1) / SCAN_CHUNK];
__device__ int   g_is64;

// ---------------------------------------------------------------------------
// Detect whether edge_index is stored as int64 (high 32-bit words all zero)
// or int32. Checks the first 2048 odd words.
// ---------------------------------------------------------------------------
__global__ __launch_bounds__(256)
void detect_kernel(const int* __restrict__ ei)
{
    __shared__ int s_or;
    if (threadIdx.x == 0) s_or = 0;
    __syncthreads();
    int o = 0;
    for (int i = threadIdx.x; i < 2048; i += 256)
        o |= ei[2 * i + 1];
    if (o) atomicOr(&s_or, 1);
    __syncthreads();
    if (threadIdx.x == 0) g_is64 = (s_or == 0) ? 1 : 0;
}

__device__ __forceinline__ int load_src(const int* ei, int E, int i, int is64)
{
    return is64 ? ei[2 * i] : ei[i];
}
__device__ __forceinline__ int load_dst(const int* ei, int E, int i, int is64)
{
    return is64 ? ei[2 * E + 2 * i] : ei[E + i];
}

// ---------------------------------------------------------------------------
// CSR build (by destination). Only integer atomics.
// ---------------------------------------------------------------------------
__global__ __launch_bounds__(256)
void zero_cnt_kernel(int n)
{
    int i = blockIdx.x * blockDim.x + threadIdx.x;
    if (i < n) g_cnt[i] = 0;
}

__global__ __launch_bounds__(256)
void hist_kernel(const int* __restrict__ ei, int E)
{
    int i = blockIdx.x * blockDim.x + threadIdx.x;
    int is64 = g_is64;
    if (i < E) atomicAdd(&g_cnt[load_dst(ei, E, i, is64)], 1);
}

// ---------------------------------------------------------------------------
// 3-phase parallel exclusive scan over g_cnt[0..n) -> g_off/g_cur, g_off[n]=E
// ---------------------------------------------------------------------------
__device__ __forceinline__ int block_exscan256(int v, int* sh)
{
    const int t = threadIdx.x;
    sh[t] = v;
    __syncthreads();
#pragma unroll
    for (int off = 1; off < 256; off <<= 1) {
        int u = (t >= off) ? sh[t - off] : 0;
        __syncthreads();
        sh[t] += u;
        __syncthreads();
    }
    return sh[t] - v;
}

__global__ __launch_bounds__(256)
void scan_partial(int n)
{
    __shared__ int sh[256];
    const int t = threadIdx.x;
    const int base = blockIdx.x * SCAN_CHUNK + t * 4;
    int s = 0;
#pragma unroll
    for (int j = 0; j < 4; j++)
        if (base + j < n) s += g_cnt[base + j];
    sh[t] = s;
    __syncthreads();
    for (int off = 128; off; off >>= 1) {
        if (t < off) sh[t] += sh[t + off];
        __syncthreads();
    }
    if (t == 0) g_bsums[blockIdx.x] = sh[0];
}

__global__ __launch_bounds__(256)
void scan_bsums(int nb)
{
    __shared__ int sh[256];
    const int t = threadIdx.x;
    int v = (t < nb) ? g_bsums[t] : 0;
    int ex = block_exscan256(v, sh);
    if (t < nb) g_boff[t] = ex;
}

__global__ __launch_bounds__(256)
void scan_final(int n, int E)
{
    __shared__ int sh[256];
    const int t = threadIdx.x;
    const int base = blockIdx.x * SCAN_CHUNK + t * 4;
    int c[4];
    int s = 0;
#pragma unroll
    for (int j = 0; j < 4; j++) {
        c[j] = (base + j < n) ? g_cnt[base + j] : 0;
        s += c[j];
    }
    int ex = block_exscan256(s, sh) + g_boff[blockIdx.x];
#pragma unroll
    for (int j = 0; j < 4; j++) {
        if (base + j < n) {
            g_off[base + j] = ex;
            g_cur[base + j] = ex;
        }
        ex += c[j];
    }
    if (blockIdx.x == 0 && t == 0) g_off[n] = E;
}

__global__ __launch_bounds__(256)
void scatter_kernel(const int* __restrict__ ei, int E)
{
    int i = blockIdx.x * blockDim.x + threadIdx.x;
    if (i >= E) return;
    int is64 = g_is64;
    int d = load_dst(ei, E, i, is64);
    int s = load_src(ei, E, i, is64);
    int pos = atomicAdd(&g_cur[d], 1);
    g_srcs[pos] = s;
}

// ---------------------------------------------------------------------------
// Fused GEMM + attention-logit epilogue.
//   xp = X @ W  (X:[n,K], W:[K,64])  -> g_xp
//   al_src[n,h] = <xp[n,h,:], att_s[h,:]>  -> g_als ; al_dst -> g_ald
// Block: 256 thr, tile 128 rows x 64 cols, thread tile 8 rows x 4 cols.
// Inner loop per k: 3x LDS.128 (all broadcast/conflict-free) + 32 FFMA.
// ---------------------------------------------------------------------------
template<int K, bool FIRST>
__global__ __launch_bounds__(256)
void gemm_al_kernel(const float* __restrict__ Xin,
                    const float* __restrict__ W,
                    const float* __restrict__ att_s,
                    const float* __restrict__ att_d,
                    int n)
{
    const float* __restrict__ X = FIRST ? Xin : g_h;

    __shared__ __align__(16) float sW[64 * 64];      // 16 KB
    __shared__ __align__(16) float sXT[64][132];     // k-major, 128 rows, pad

    const int tid = threadIdx.x;
    const int cx  = tid & 15;           // col group (4 cols)
    const int ry  = tid >> 4;           // row group (8 rows)
    const int row0 = blockIdx.x * 128;

    float C[8][4];
#pragma unroll
    for (int i = 0; i < 8; i++)
#pragma unroll
        for (int j = 0; j < 4; j++) C[i][j] = 0.f;

    for (int kc = 0; kc < K; kc += 64) {
        __syncthreads();
        // load W chunk (4096 contiguous floats)
#pragma unroll
        for (int q = 0; q < 4; q++) {
            int idx4 = tid + q * 256;
            float4 v = *(const float4*)&W[kc * 64 + idx4 * 4];
            *(float4*)&sW[idx4 * 4] = v;
        }
        // load X tile transposed: 128 rows x 64 k
#pragma unroll
        for (int q = 0; q < 8; q++) {
            int lin = tid + q * 256;
            int r  = lin >> 4;
            int c4 = lin & 15;
            int gr = row0 + r; if (gr > n - 1) gr = n - 1;
            float4 v = *(const float4*)&X[(long long)gr * K + kc + c4 * 4];
            sXT[c4 * 4 + 0][r] = v.x;
            sXT[c4 * 4 + 1][r] = v.y;
            sXT[c4 * 4 + 2][r] = v.z;
            sXT[c4 * 4 + 3][r] = v.w;
        }
        __syncthreads();
#pragma unroll
        for (int k = 0; k < 64; k++) {
            float4 wv = *(const float4*)&sW[k * 64 + cx * 4];
            float4 xa = *(const float4*)&sXT[k][ry * 8];
            float4 xb = *(const float4*)&sXT[k][ry * 8 + 4];
            float xr[8] = {xa.x, xa.y, xa.z, xa.w, xb.x, xb.y, xb.z, xb.w};
#pragma unroll
            for (int i = 0; i < 8; i++) {
                C[i][0] = fmaf(xr[i], wv.x, C[i][0]);
                C[i][1] = fmaf(xr[i], wv.y, C[i][1]);
                C[i][2] = fmaf(xr[i], wv.z, C[i][2]);
                C[i][3] = fmaf(xr[i], wv.w, C[i][3]);
            }
        }
    }

    // epilogue: attention logits
    const int h    = cx >> 3;
    const int lane = tid & 31;
    float asv[4], adv[4];
#pragma unroll
    for (int j = 0; j < 4; j++) {
        asv[j] = __ldg(&att_s[cx * 4 + j]);
        adv[j] = __ldg(&att_d[cx * 4 + j]);
    }

#pragma unroll
    for (int i = 0; i < 8; i++) {
        float als = 0.f, ald = 0.f;
#pragma unroll
        for (int j = 0; j < 4; j++) {
            als = fmaf(C[i][j], asv[j], als);
            ald = fmaf(C[i][j], adv[j], ald);
        }
        // reduce across 8 lanes (one head's 32 cols)
#pragma unroll
        for (int off = 4; off; off >>= 1) {
            als += __shfl_down_sync(0xffffffffu, als, off, 8);
            ald += __shfl_down_sync(0xffffffffu, ald, off, 8);
        }
        int row = row0 + ry * 8 + i;
        if (row < n) {
            if ((lane & 7) == 0) {
                g_als[row * 2 + h] = als;
                g_ald[row * 2 + h] = ald;
            }
            *(float4*)&g_xp[row * HID + cx * 4] =
                make_float4(C[i][0], C[i][1], C[i][2], C[i][3]);
        }
    }
}

// ---------------------------------------------------------------------------
// Gather pass: one warp per destination node. No float atomics.
//   w_e = exp(lrelu(als[s]+ald[d])) ; acc += xp[s]*w ; seg += w
// Self-loop folded into init. Finish: acc/seg + bias (+ELU for layer 1).
// ---------------------------------------------------------------------------
template<bool LAST>
__global__ __launch_bounds__(256)
void gather_kernel(const float* __restrict__ bias,
                   float* __restrict__ out, int n)
{
    int warp = (blockIdx.x * 256 + threadIdx.x) >> 5;
    int lane = threadIdx.x & 31;
    if (warp >= n) return;
    const int node = warp;
    const int h = lane >> 4;            // lanes 0-15: head 0, 16-31: head 1

    const float ald_h = __ldg(&g_ald[node * 2 + h]);

    // self loop
    float t0 = __ldg(&g_als[node * 2 + h]) + ald_h;
    t0 = fmaxf(t0, 0.2f * t0);
    float w = __expf(t0);
    float2 xv = *(const float2*)&g_xp[node * HID + lane * 2];
    float a0 = xv.x * w, a1 = xv.y * w, seg = w;

    const int beg = g_off[node];
    const int end = g_off[node + 1];
    for (int i = beg; i < end; i += 32) {
        int cnt = min(32, end - i);
        int sidx = (i + lane < end) ? __ldg(&g_srcs[i + lane]) : 0;
#pragma unroll 4
        for (int j = 0; j < cnt; j++) {
            int s = __shfl_sync(0xffffffffu, sidx, j);
            float tt = __ldg(&g_als[s * 2 + h]) + ald_h;
            tt = fmaxf(tt, 0.2f * tt);
            float ww = __expf(tt);
            float2 xs = *(const float2*)&g_xp[s * HID + lane * 2];
            a0 = fmaf(xs.x, ww, a0);
            a1 = fmaf(xs.y, ww, a1);
            seg += ww;
        }
    }

    float inv = 1.f / (seg + 1e-16f);
    float2 bv = *(const float2*)&bias[lane * 2];
    float v0 = a0 * inv + bv.x;
    float v1 = a1 * inv + bv.y;
    if (!LAST) {
        v0 = v0 > 0.f ? v0 : expm1f(v0);
        v1 = v1 > 0.f ? v1 : expm1f(v1);
        *(float2*)&g_h[node * HID + lane * 2] = make_float2(v0, v1);
    } else {
        *(float2*)&out[node * HID + lane * 2] = make_float2(v0, v1);
    }
}

extern "C" void kernel_launch(void* const* d_in, const int* in_sizes, int n_in,
                              void* d_out, int out_size)
{
    const float* x   = (const float*)d_in[0];
    const int*   ei  = (const int*)d_in[1];
    const float* W1  = (const float*)d_in[2];
    const float* as1 = (const float*)d_in[3];
    const float* ad1 = (const float*)d_in[4];
    const float* b1  = (const float*)d_in[5];
    const float* W2  = (const float*)d_in[6];
    const float* as2 = (const float*)d_in[7];
    const float* ad2 = (const float*)d_in[8];
    const float* b2  = (const float*)d_in[9];

    const int n = in_sizes[0] / 128;          // 100000
    const int E = in_sizes[1] / 2;            // 1600000
    const int gb  = (n + 127) / 128;
    const int nbl = (n + 255) / 256;
    const int ebl = (E + 255) / 256;
    const int wbl = ((n * 32) + 255) / 256;   // warp per node
    const int sb  = (n + SCAN_CHUNK - 1) / SCAN_CHUNK;

    // CSR build (graph is shared by both layers)
    detect_kernel<<<1, 256>>>(ei);
    zero_cnt_kernel<<<nbl, 256>>>(n);
    hist_kernel<<<ebl, 256>>>(ei, E);
    scan_partial<<<sb, 256>>>(n);
    scan_bsums<<<1, 256>>>(sb);
    scan_final<<<sb, 256>>>(n, E);
    scatter_kernel<<<ebl, 256>>>(ei, E);

    // layer 1
    gemm_al_kernel<128, true><<<gb, 256>>>(x, W1, as1, ad1, n);
    gather_kernel<false><<<wbl, 256>>>(b1, nullptr, n);
    // layer 2
    gemm_al_kernel<64, false><<<gb, 256>>>(x, W2, as2, ad2, n);
    gather_kernel<true><<<wbl, 256>>>(b2, (float*)d_out, n);
}

// round 8
// speedup vs baseline: 1.2058x; 1.0725x over previous
#include <cuda_runtime.h>

#define NMAX 100000
#define EMAX 1600000
#define HID 64
#define SCAN_CHUNK 1024   // elements per scan block (256 thr * 4)

// scratch (no cudaMalloc allowed)
__device__ __align__(16) float g_xp [NMAX * HID];
__device__ __align__(16) float g_h  [NMAX * HID];
__device__ float g_als[NMAX * 2];
__device__ float g_ald[NMAX * 2];
__device__ int   g_cnt[NMAX];
__device__ int   g_off[NMAX + 1];
__device__ int   g_cur[NMAX];
__device__ int   g_srcs[EMAX];
__device__ int   g_bsums[(NMAX + SCAN_CHUNK - 1) / SCAN_CHUNK];
__device__ int   g_boff [(NMAX + SCAN_CHUNK - 1) / SCAN_CHUNK];
__device__ int   g_is64;

// ---------------------------------------------------------------------------
// Detect whether edge_index is stored as int64 (high 32-bit words all zero)
// or int32. Checks the first 2048 odd words.
// ---------------------------------------------------------------------------
__global__ __launch_bounds__(256)
void detect_kernel(const int* __restrict__ ei)
{
    __shared__ int s_or;
    if (threadIdx.x == 0) s_or = 0;
    __syncthreads();
    int o = 0;
    for (int i = threadIdx.x; i < 2048; i += 256)
        o |= ei[2 * i + 1];
    if (o) atomicOr(&s_or, 1);
    __syncthreads();
    if (threadIdx.x == 0) g_is64 = (s_or == 0) ? 1 : 0;
}

__device__ __forceinline__ int load_src(const int* ei, int E, int i, int is64)
{
    return is64 ? ei[2 * i] : ei[i];
}
__device__ __forceinline__ int load_dst(const int* ei, int E, int i, int is64)
{
    return is64 ? ei[2 * E + 2 * i] : ei[E + i];
}

// ---------------------------------------------------------------------------
// CSR build (by destination). Only integer atomics.
// ---------------------------------------------------------------------------
__global__ __launch_bounds__(256)
void zero_cnt_kernel(int n)
{
    int i = blockIdx.x * blockDim.x + threadIdx.x;
    if (i < n) g_cnt[i] = 0;
}

__global__ __launch_bounds__(256)
void hist_kernel(const int* __restrict__ ei, int E)
{
    int i = blockIdx.x * blockDim.x + threadIdx.x;
    int is64 = g_is64;
    if (i < E) atomicAdd(&g_cnt[load_dst(ei, E, i, is64)], 1);
}

// ---------------------------------------------------------------------------
// 3-phase parallel exclusive scan over g_cnt[0..n) -> g_off/g_cur, g_off[n]=E
// ---------------------------------------------------------------------------
__device__ __forceinline__ int block_exscan256(int v, int* sh)
{
    const int t = threadIdx.x;
    sh[t] = v;
    __syncthreads();
#pragma unroll
    for (int off = 1; off < 256; off <<= 1) {
        int u = (t >= off) ? sh[t - off] : 0;
        __syncthreads();
        sh[t] += u;
        __syncthreads();
    }
    return sh[t] - v;
}

__global__ __launch_bounds__(256)
void scan_partial(int n)
{
    __shared__ int sh[256];
    const int t = threadIdx.x;
    const int base = blockIdx.x * SCAN_CHUNK + t * 4;
    int s = 0;
#pragma unroll
    for (int j = 0; j < 4; j++)
        if (base + j < n) s += g_cnt[base + j];
    sh[t] = s;
    __syncthreads();
    for (int off = 128; off; off >>= 1) {
        if (t < off) sh[t] += sh[t + off];
        __syncthreads();
    }
    if (t == 0) g_bsums[blockIdx.x] = sh[0];
}

__global__ __launch_bounds__(256)
void scan_bsums(int nb)
{
    __shared__ int sh[256];
    const int t = threadIdx.x;
    int v = (t < nb) ? g_bsums[t] : 0;
    int ex = block_exscan256(v, sh);
    if (t < nb) g_boff[t] = ex;
}

__global__ __launch_bounds__(256)
void scan_final(int n, int E)
{
    __shared__ int sh[256];
    const int t = threadIdx.x;
    const int base = blockIdx.x * SCAN_CHUNK + t * 4;
    int c[4];
    int s = 0;
#pragma unroll
    for (int j = 0; j < 4; j++) {
        c[j] = (base + j < n) ? g_cnt[base + j] : 0;
        s += c[j];
    }
    int ex = block_exscan256(s, sh) + g_boff[blockIdx.x];
#pragma unroll
    for (int j = 0; j < 4; j++) {
        if (base + j < n) {
            g_off[base + j] = ex;
            g_cur[base + j] = ex;
        }
        ex += c[j];
    }
    if (blockIdx.x == 0 && t == 0) g_off[n] = E;
}

__global__ __launch_bounds__(256)
void scatter_kernel(const int* __restrict__ ei, int E)
{
    int i = blockIdx.x * blockDim.x + threadIdx.x;
    if (i >= E) return;
    int is64 = g_is64;
    int d = load_dst(ei, E, i, is64);
    int s = load_src(ei, E, i, is64);
    int pos = atomicAdd(&g_cur[d], 1);
    g_srcs[pos] = s;
}

// ---------------------------------------------------------------------------
// Fused GEMM + attention-logit epilogue.
//   xp = X @ W  (X:[n,K], W:[K,64])  -> g_xp
//   al_src[n,h] = <xp[n,h,:], att_s[h,:]>  -> g_als ; al_dst -> g_ald
// Block: 256 thr, tile 128 rows x 64 cols, thread tile 8 rows x 4 cols.
// ---------------------------------------------------------------------------
template<int K, bool FIRST>
__global__ __launch_bounds__(256)
void gemm_al_kernel(const float* __restrict__ Xin,
                    const float* __restrict__ W,
                    const float* __restrict__ att_s,
                    const float* __restrict__ att_d,
                    int n)
{
    const float* __restrict__ X = FIRST ? Xin : g_h;

    __shared__ __align__(16) float sW[64 * 64];      // 16 KB
    __shared__ __align__(16) float sXT[64][132];     // k-major, 128 rows, pad

    const int tid = threadIdx.x;
    const int cx  = tid & 15;           // col group (4 cols)
    const int ry  = tid >> 4;           // row group (8 rows)
    const int row0 = blockIdx.x * 128;

    float C[8][4];
#pragma unroll
    for (int i = 0; i < 8; i++)
#pragma unroll
        for (int j = 0; j < 4; j++) C[i][j] = 0.f;

    for (int kc = 0; kc < K; kc += 64) {
        __syncthreads();
#pragma unroll
        for (int q = 0; q < 4; q++) {
            int idx4 = tid + q * 256;
            float4 v = *(const float4*)&W[kc * 64 + idx4 * 4];
            *(float4*)&sW[idx4 * 4] = v;
        }
#pragma unroll
        for (int q = 0; q < 8; q++) {
            int lin = tid + q * 256;
            int r  = lin >> 4;
            int c4 = lin & 15;
            int gr = row0 + r; if (gr > n - 1) gr = n - 1;
            float4 v = *(const float4*)&X[(long long)gr * K + kc + c4 * 4];
            sXT[c4 * 4 + 0][r] = v.x;
            sXT[c4 * 4 + 1][r] = v.y;
            sXT[c4 * 4 + 2][r] = v.z;
            sXT[c4 * 4 + 3][r] = v.w;
        }
        __syncthreads();
#pragma unroll
        for (int k = 0; k < 64; k++) {
            float4 wv = *(const float4*)&sW[k * 64 + cx * 4];
            float4 xa = *(const float4*)&sXT[k][ry * 8];
            float4 xb = *(const float4*)&sXT[k][ry * 8 + 4];
            float xr[8] = {xa.x, xa.y, xa.z, xa.w, xb.x, xb.y, xb.z, xb.w};
#pragma unroll
            for (int i = 0; i < 8; i++) {
                C[i][0] = fmaf(xr[i], wv.x, C[i][0]);
                C[i][1] = fmaf(xr[i], wv.y, C[i][1]);
                C[i][2] = fmaf(xr[i], wv.z, C[i][2]);
                C[i][3] = fmaf(xr[i], wv.w, C[i][3]);
            }
        }
    }

    // epilogue: attention logits
    const int h    = cx >> 3;
    const int lane = tid & 31;
    float asv[4], adv[4];
#pragma unroll
    for (int j = 0; j < 4; j++) {
        asv[j] = __ldg(&att_s[cx * 4 + j]);
        adv[j] = __ldg(&att_d[cx * 4 + j]);
    }

#pragma unroll
    for (int i = 0; i < 8; i++) {
        float als = 0.f, ald = 0.f;
#pragma unroll
        for (int j = 0; j < 4; j++) {
            als = fmaf(C[i][j], asv[j], als);
            ald = fmaf(C[i][j], adv[j], ald);
        }
#pragma unroll
        for (int off = 4; off; off >>= 1) {
            als += __shfl_down_sync(0xffffffffu, als, off, 8);
            ald += __shfl_down_sync(0xffffffffu, ald, off, 8);
        }
        int row = row0 + ry * 8 + i;
        if (row < n) {
            if ((lane & 7) == 0) {
                g_als[row * 2 + h] = als;
                g_ald[row * 2 + h] = ald;
            }
            *(float4*)&g_xp[row * HID + cx * 4] =
                make_float4(C[i][0], C[i][1], C[i][2], C[i][3]);
        }
    }
}

// ---------------------------------------------------------------------------
// Gather pass: one warp per destination node. No float atomics.
// ---------------------------------------------------------------------------
template<bool LAST>
__global__ __launch_bounds__(256)
void gather_kernel(const float* __restrict__ bias,
                   float* __restrict__ out, int n)
{
    int warp = (blockIdx.x * 256 + threadIdx.x) >> 5;
    int lane = threadIdx.x & 31;
    if (warp >= n) return;
    const int node = warp;
    const int h = lane >> 4;            // lanes 0-15: head 0, 16-31: head 1

    const float ald_h = __ldg(&g_ald[node * 2 + h]);

    // self loop
    float t0 = __ldg(&g_als[node * 2 + h]) + ald_h;
    t0 = fmaxf(t0, 0.2f * t0);
    float w = __expf(t0);
    float2 xv = *(const float2*)&g_xp[node * HID + lane * 2];
    float a0 = xv.x * w, a1 = xv.y * w, seg = w;

    const int beg = g_off[node];
    const int end = g_off[node + 1];
    for (int i = beg; i < end; i += 32) {
        int cnt = min(32, end - i);
        int sidx = (i + lane < end) ? __ldg(&g_srcs[i + lane]) : 0;
#pragma unroll 4
        for (int j = 0; j < cnt; j++) {
            int s = __shfl_sync(0xffffffffu, sidx, j);
            float tt = __ldg(&g_als[s * 2 + h]) + ald_h;
            tt = fmaxf(tt, 0.2f * tt);
            float ww = __expf(tt);
            float2 xs = *(const float2*)&g_xp[s * HID + lane * 2];
            a0 = fmaf(xs.x, ww, a0);
            a1 = fmaf(xs.y, ww, a1);
            seg += ww;
        }
    }

    float inv = 1.f / (seg + 1e-16f);
    float2 bv = *(const float2*)&bias[lane * 2];
    float v0 = a0 * inv + bv.x;
    float v1 = a1 * inv + bv.y;
    if (!LAST) {
        v0 = v0 > 0.f ? v0 : expm1f(v0);
        v1 = v1 > 0.f ? v1 : expm1f(v1);
        *(float2*)&g_h[node * HID + lane * 2] = make_float2(v0, v1);
    } else {
        *(float2*)&out[node * HID + lane * 2] = make_float2(v0, v1);
    }
}

extern "C" void kernel_launch(void* const* d_in, const int* in_sizes, int n_in,
                              void* d_out, int out_size)
{
    const float* x   = (const float*)d_in[0];
    const int*   ei  = (const int*)d_in[1];
    const float* W1  = (const float*)d_in[2];
    const float* as1 = (const float*)d_in[3];
    const float* ad1 = (const float*)d_in[4];
    const float* b1  = (const float*)d_in[5];
    const float* W2  = (const float*)d_in[6];
    const float* as2 = (const float*)d_in[7];
    const float* ad2 = (const float*)d_in[8];
    const float* b2  = (const float*)d_in[9];

    const int n = in_sizes[0] / 128;          // 100000
    const int E = in_sizes[1] / 2;            // 1600000
    const int gb  = (n + 127) / 128;
    const int nbl = (n + 255) / 256;
    const int ebl = (E + 255) / 256;
    const int wbl = ((n * 32) + 255) / 256;   // warp per node
    const int sb  = (n + SCAN_CHUNK - 1) / SCAN_CHUNK;

    // one-time stream/event setup (host-side only; identical graph each call)
    static cudaStream_t sCsr = nullptr, sMain = nullptr;
    static cudaEvent_t evFork = nullptr, evCsr = nullptr, evDone = nullptr;
    if (!sCsr) {
        cudaStreamCreateWithFlags(&sCsr,  cudaStreamNonBlocking);
        cudaStreamCreateWithFlags(&sMain, cudaStreamNonBlocking);
        cudaEventCreateWithFlags(&evFork, cudaEventDisableTiming);
        cudaEventCreateWithFlags(&evCsr,  cudaEventDisableTiming);
        cudaEventCreateWithFlags(&evDone, cudaEventDisableTiming);
    }

    // fork from the (capturing) default stream
    cudaEventRecord(evFork, 0);
    cudaStreamWaitEvent(sCsr,  evFork, 0);
    cudaStreamWaitEvent(sMain, evFork, 0);

    // CSR build chain (independent of gemm1) on sCsr
    detect_kernel<<<1, 256, 0, sCsr>>>(ei);
    zero_cnt_kernel<<<nbl, 256, 0, sCsr>>>(n);
    hist_kernel<<<ebl, 256, 0, sCsr>>>(ei, E);
    scan_partial<<<sb, 256, 0, sCsr>>>(n);
    scan_bsums<<<1, 256, 0, sCsr>>>(sb);
    scan_final<<<sb, 256, 0, sCsr>>>(n, E);
    scatter_kernel<<<ebl, 256, 0, sCsr>>>(ei, E);
    cudaEventRecord(evCsr, sCsr);

    // layer 1 GEMM concurrently on sMain
    gemm_al_kernel<128, true><<<gb, 256, 0, sMain>>>(x, W1, as1, ad1, n);

    // join: gather1 needs both gemm1 and the CSR
    cudaStreamWaitEvent(sMain, evCsr, 0);
    gather_kernel<false><<<wbl, 256, 0, sMain>>>(b1, nullptr, n);
    // layer 2
    gemm_al_kernel<64, false><<<gb, 256, 0, sMain>>>(x, W2, as2, ad2, n);
    gather_kernel<true><<<wbl, 256, 0, sMain>>>(b2, (float*)d_out, n);

    // join back to the default (capture-origin) stream
    cudaEventRecord(evDone, sMain);
    cudaStreamWaitEvent(0, evDone, 0);
}

// round 9
// speedup vs baseline: 1.2744x; 1.0569x over previous
#include <cuda_runtime.h>

#define NMAX 100000
#define EMAX 1600000
#define HID 64
#define SCAN_CHUNK 1024   // elements per scan block (256 thr * 4)

// scratch (no cudaMalloc allowed)
__device__ __align__(16) float g_xp [NMAX * HID];
__device__ __align__(16) float g_h  [NMAX * HID];
__device__ float g_als[NMAX * 2];
__device__ float g_ald[NMAX * 2];
__device__ int   g_cnt[NMAX];
__device__ int   g_off[NMAX + 1];
__device__ int   g_cur[NMAX];
__device__ int   g_srcs[EMAX];
__device__ int   g_bsums[(NMAX + SCAN_CHUNK - 1) / SCAN_CHUNK];
__device__ int   g_boff [(NMAX + SCAN_CHUNK - 1) / SCAN_CHUNK];
__device__ int   g_is64;

// ---------------------------------------------------------------------------
// Detect whether edge_index is stored as int64 (high words zero) or int32.
// ---------------------------------------------------------------------------
__global__ __launch_bounds__(256)
void detect_kernel(const int* __restrict__ ei)
{
    __shared__ int s_or;
    if (threadIdx.x == 0) s_or = 0;
    __syncthreads();
    int o = 0;
    for (int i = threadIdx.x; i < 2048; i += 256)
        o |= ei[2 * i + 1];
    if (o) atomicOr(&s_or, 1);
    __syncthreads();
    if (threadIdx.x == 0) g_is64 = (s_or == 0) ? 1 : 0;
}

__device__ __forceinline__ int load_src(const int* ei, int E, int i, int is64)
{
    return is64 ? ei[2 * i] : ei[i];
}
__device__ __forceinline__ int load_dst(const int* ei, int E, int i, int is64)
{
    return is64 ? ei[2 * E + 2 * i] : ei[E + i];
}

// ---------------------------------------------------------------------------
// CSR build (by destination). Only integer atomics.
// ---------------------------------------------------------------------------
__global__ __launch_bounds__(256)
void zero_cnt_kernel(int n)
{
    int i = blockIdx.x * blockDim.x + threadIdx.x;
    if (i < n) g_cnt[i] = 0;
}

__global__ __launch_bounds__(256)
void hist_kernel(const int* __restrict__ ei, int E)
{
    int i = blockIdx.x * blockDim.x + threadIdx.x;
    int is64 = g_is64;
    if (i < E) atomicAdd(&g_cnt[load_dst(ei, E, i, is64)], 1);
}

__device__ __forceinline__ int block_exscan256(int v, int* sh)
{
    const int t = threadIdx.x;
    sh[t] = v;
    __syncthreads();
#pragma unroll
    for (int off = 1; off < 256; off <<= 1) {
        int u = (t >= off) ? sh[t - off] : 0;
        __syncthreads();
        sh[t] += u;
        __syncthreads();
    }
    return sh[t] - v;
}

__global__ __launch_bounds__(256)
void scan_partial(int n)
{
    __shared__ int sh[256];
    const int t = threadIdx.x;
    const int base = blockIdx.x * SCAN_CHUNK + t * 4;
    int s = 0;
#pragma unroll
    for (int j = 0; j < 4; j++)
        if (base + j < n) s += g_cnt[base + j];
    sh[t] = s;
    __syncthreads();
    for (int off = 128; off; off >>= 1) {
        if (t < off) sh[t] += sh[t + off];
        __syncthreads();
    }
    if (t == 0) g_bsums[blockIdx.x] = sh[0];
}

__global__ __launch_bounds__(256)
void scan_bsums(int nb)
{
    __shared__ int sh[256];
    const int t = threadIdx.x;
    int v = (t < nb) ? g_bsums[t] : 0;
    int ex = block_exscan256(v, sh);
    if (t < nb) g_boff[t] = ex;
}

__global__ __launch_bounds__(256)
void scan_final(int n, int E)
{
    __shared__ int sh[256];
    const int t = threadIdx.x;
    const int base = blockIdx.x * SCAN_CHUNK + t * 4;
    int c[4];
    int s = 0;
#pragma unroll
    for (int j = 0; j < 4; j++) {
        c[j] = (base + j < n) ? g_cnt[base + j] : 0;
        s += c[j];
    }
    int ex = block_exscan256(s, sh) + g_boff[blockIdx.x];
#pragma unroll
    for (int j = 0; j < 4; j++) {
        if (base + j < n) {
            g_off[base + j] = ex;
            g_cur[base + j] = ex;
        }
        ex += c[j];
    }
    if (blockIdx.x == 0 && t == 0) g_off[n] = E;
}

__global__ __launch_bounds__(256)
void scatter_kernel(const int* __restrict__ ei, int E)
{
    int i = blockIdx.x * blockDim.x + threadIdx.x;
    if (i >= E) return;
    int is64 = g_is64;
    int d = load_dst(ei, E, i, is64);
    int s = load_src(ei, E, i, is64);
    int pos = atomicAdd(&g_cur[d], 1);
    g_srcs[pos] = s;
}

// ---------------------------------------------------------------------------
// Fused GEMM + attention-logit epilogue (unchanged from R7 winner).
// ---------------------------------------------------------------------------
template<int K, bool FIRST>
__global__ __launch_bounds__(256)
void gemm_al_kernel(const float* __restrict__ Xin,
                    const float* __restrict__ W,
                    const float* __restrict__ att_s,
                    const float* __restrict__ att_d,
                    int n)
{
    const float* __restrict__ X = FIRST ? Xin : g_h;

    __shared__ __align__(16) float sW[64 * 64];
    __shared__ __align__(16) float sXT[64][132];

    const int tid = threadIdx.x;
    const int cx  = tid & 15;
    const int ry  = tid >> 4;
    const int row0 = blockIdx.x * 128;

    float C[8][4];
#pragma unroll
    for (int i = 0; i < 8; i++)
#pragma unroll
        for (int j = 0; j < 4; j++) C[i][j] = 0.f;

    for (int kc = 0; kc < K; kc += 64) {
        __syncthreads();
#pragma unroll
        for (int q = 0; q < 4; q++) {
            int idx4 = tid + q * 256;
            float4 v = *(const float4*)&W[kc * 64 + idx4 * 4];
            *(float4*)&sW[idx4 * 4] = v;
        }
#pragma unroll
        for (int q = 0; q < 8; q++) {
            int lin = tid + q * 256;
            int r  = lin >> 4;
            int c4 = lin & 15;
            int gr = row0 + r; if (gr > n - 1) gr = n - 1;
            float4 v = *(const float4*)&X[(long long)gr * K + kc + c4 * 4];
            sXT[c4 * 4 + 0][r] = v.x;
            sXT[c4 * 4 + 1][r] = v.y;
            sXT[c4 * 4 + 2][r] = v.z;
            sXT[c4 * 4 + 3][r] = v.w;
        }
        __syncthreads();
#pragma unroll
        for (int k = 0; k < 64; k++) {
            float4 wv = *(const float4*)&sW[k * 64 + cx * 4];
            float4 xa = *(const float4*)&sXT[k][ry * 8];
            float4 xb = *(const float4*)&sXT[k][ry * 8 + 4];
            float xr[8] = {xa.x, xa.y, xa.z, xa.w, xb.x, xb.y, xb.z, xb.w};
#pragma unroll
            for (int i = 0; i < 8; i++) {
                C[i][0] = fmaf(xr[i], wv.x, C[i][0]);
                C[i][1] = fmaf(xr[i], wv.y, C[i][1]);
                C[i][2] = fmaf(xr[i], wv.z, C[i][2]);
                C[i][3] = fmaf(xr[i], wv.w, C[i][3]);
            }
        }
    }

    const int h    = cx >> 3;
    const int lane = tid & 31;
    float asv[4], adv[4];
#pragma unroll
    for (int j = 0; j < 4; j++) {
        asv[j] = __ldg(&att_s[cx * 4 + j]);
        adv[j] = __ldg(&att_d[cx * 4 + j]);
    }

#pragma unroll
    for (int i = 0; i < 8; i++) {
        float als = 0.f, ald = 0.f;
#pragma unroll
        for (int j = 0; j < 4; j++) {
            als = fmaf(C[i][j], asv[j], als);
            ald = fmaf(C[i][j], adv[j], ald);
        }
#pragma unroll
        for (int off = 4; off; off >>= 1) {
            als += __shfl_down_sync(0xffffffffu, als, off, 8);
            ald += __shfl_down_sync(0xffffffffu, ald, off, 8);
        }
        int row = row0 + ry * 8 + i;
        if (row < n) {
            if ((lane & 7) == 0) {
                g_als[row * 2 + h] = als;
                g_ald[row * 2 + h] = ald;
            }
            *(float4*)&g_xp[row * HID + cx * 4] =
                make_float4(C[i][0], C[i][1], C[i][2], C[i][3]);
        }
    }
}

// ---------------------------------------------------------------------------
// Gather pass v2: one warp per destination node, half-warp per head.
// Lanes batch-compute 16 edges' softmax weights in parallel (MLP=16 on
// logit loads, parallel MUFU), then a tight j-loop does 2 shfl + LDG.64 +
// 2 FMA per edge. Per-lane seg accumulation, reduced once at the end.
// ---------------------------------------------------------------------------
template<bool LAST>
__global__ __launch_bounds__(256)
void gather_kernel(const float* __restrict__ bias,
                   float* __restrict__ out, int n)
{
    int warp = (blockIdx.x * 256 + threadIdx.x) >> 5;
    int lane = threadIdx.x & 31;
    if (warp >= n) return;
    const int node = warp;
    const int h  = lane >> 4;           // half-warp = head
    const int hl = lane & 15;           // lane within half

    const float ald_h = __ldg(&g_ald[node * 2 + h]);

    // self loop (per-lane for its head)
    float t0 = __ldg(&g_als[node * 2 + h]) + ald_h;
    t0 = fmaxf(t0, 0.2f * t0);
    float wself = __expf(t0);
    float2 xv = *(const float2*)&g_xp[node * HID + lane * 2];
    float a0 = xv.x * wself, a1 = xv.y * wself;
    float segl = 0.f;                   // per-lane partial (own head)

    const int beg = g_off[node];
    const int end = g_off[node + 1];
    for (int i = beg; i < end; i += 16) {
        int idx = i + hl;
        bool valid = idx < end;
        int sidx = valid ? __ldg(&g_srcs[idx]) : 0;
        float al = __ldg(&g_als[sidx * 2 + h]);
        float tt = al + ald_h;
        tt = fmaxf(tt, 0.2f * tt);
        float w = valid ? __expf(tt) : 0.f;
        segl += w;

        int cnt = min(16, end - i);
#pragma unroll 4
        for (int j = 0; j < cnt; j++) {
            float ww = __shfl_sync(0xffffffffu, w, j, 16);
            int   s  = __shfl_sync(0xffffffffu, sidx, j, 16);
            float2 xs = *(const float2*)&g_xp[s * HID + lane * 2];
            a0 = fmaf(xs.x, ww, a0);
            a1 = fmaf(xs.y, ww, a1);
        }
    }

    // reduce seg within each half-warp
#pragma unroll
    for (int off = 8; off; off >>= 1)
        segl += __shfl_xor_sync(0xffffffffu, segl, off, 16);
    float seg = segl + wself;

    float inv = 1.f / (seg + 1e-16f);
    float2 bv = *(const float2*)&bias[lane * 2];
    float v0 = a0 * inv + bv.x;
    float v1 = a1 * inv + bv.y;
    if (!LAST) {
        v0 = v0 > 0.f ? v0 : expm1f(v0);
        v1 = v1 > 0.f ? v1 : expm1f(v1);
        *(float2*)&g_h[node * HID + lane * 2] = make_float2(v0, v1);
    } else {
        *(float2*)&out[node * HID + lane * 2] = make_float2(v0, v1);
    }
}

extern "C" void kernel_launch(void* const* d_in, const int* in_sizes, int n_in,
                              void* d_out, int out_size)
{
    const float* x   = (const float*)d_in[0];
    const int*   ei  = (const int*)d_in[1];
    const float* W1  = (const float*)d_in[2];
    const float* as1 = (const float*)d_in[3];
    const float* ad1 = (const float*)d_in[4];
    const float* b1  = (const float*)d_in[5];
    const float* W2  = (const float*)d_in[6];
    const float* as2 = (const float*)d_in[7];
    const float* ad2 = (const float*)d_in[8];
    const float* b2  = (const float*)d_in[9];

    const int n = in_sizes[0] / 128;          // 100000
    const int E = in_sizes[1] / 2;            // 1600000
    const int gb  = (n + 127) / 128;
    const int nbl = (n + 255) / 256;
    const int ebl = (E + 255) / 256;
    const int wbl = ((n * 32) + 255) / 256;
    const int sb  = (n + SCAN_CHUNK - 1) / SCAN_CHUNK;

    static cudaStream_t sCsr = nullptr, sMain = nullptr;
    static cudaEvent_t evFork = nullptr, evCsr = nullptr, evDone = nullptr;
    if (!sCsr) {
        cudaStreamCreateWithFlags(&sCsr,  cudaStreamNonBlocking);
        cudaStreamCreateWithFlags(&sMain, cudaStreamNonBlocking);
        cudaEventCreateWithFlags(&evFork, cudaEventDisableTiming);
        cudaEventCreateWithFlags(&evCsr,  cudaEventDisableTiming);
        cudaEventCreateWithFlags(&evDone, cudaEventDisableTiming);
    }

    cudaEventRecord(evFork, 0);
    cudaStreamWaitEvent(sCsr,  evFork, 0);
    cudaStreamWaitEvent(sMain, evFork, 0);

    // launches #0..#2 on sCsr
    detect_kernel<<<1, 256, 0, sCsr>>>(ei);
    zero_cnt_kernel<<<nbl, 256, 0, sCsr>>>(n);
    hist_kernel<<<ebl, 256, 0, sCsr>>>(ei, E);
    // launch #3 = gemm1 (profiled by ncu's fixed skip)
    gemm_al_kernel<128, true><<<gb, 256, 0, sMain>>>(x, W1, as1, ad1, n);
    // rest of CSR chain
    scan_partial<<<sb, 256, 0, sCsr>>>(n);
    scan_bsums<<<1, 256, 0, sCsr>>>(sb);
    scan_final<<<sb, 256, 0, sCsr>>>(n, E);
    scatter_kernel<<<ebl, 256, 0, sCsr>>>(ei, E);
    cudaEventRecord(evCsr, sCsr);

    // join: gather1 needs both gemm1 and the CSR
    cudaStreamWaitEvent(sMain, evCsr, 0);
    gather_kernel<false><<<wbl, 256, 0, sMain>>>(b1, nullptr, n);
    gemm_al_kernel<64, false><<<gb, 256, 0, sMain>>>(x, W2, as2, ad2, n);
    gather_kernel<true><<<wbl, 256, 0, sMain>>>(b2, (float*)d_out, n);

    cudaEventRecord(evDone, sMain);
    cudaStreamWaitEvent(0, evDone, 0);
}

// round 10
// speedup vs baseline: 1.2776x; 1.0025x over previous
#include <cuda_runtime.h>
#include <cuda_fp16.h>

#define NMAX 100000
#define EMAX 1600000
#define HID 64
#define SCAN_CHUNK 1024   // elements per scan block (256 thr * 4)

// scratch (no cudaMalloc allowed)
__device__ __align__(16) __half g_xp [NMAX * HID];   // fp16 message payload
__device__ __align__(16) float  g_h  [NMAX * HID];
__device__ float g_als[NMAX * 2];
__device__ float g_ald[NMAX * 2];
__device__ int   g_cnt[NMAX];
__device__ int   g_off[NMAX + 1];
__device__ int   g_cur[NMAX];
__device__ int   g_srcs[EMAX];
__device__ int   g_bsums[(NMAX + SCAN_CHUNK - 1) / SCAN_CHUNK];
__device__ int   g_boff [(NMAX + SCAN_CHUNK - 1) / SCAN_CHUNK];
__device__ int   g_is64;

// ---------------------------------------------------------------------------
// Detect whether edge_index is stored as int64 (high words zero) or int32.
// ---------------------------------------------------------------------------
__global__ __launch_bounds__(256)
void detect_kernel(const int* __restrict__ ei)
{
    __shared__ int s_or;
    if (threadIdx.x == 0) s_or = 0;
    __syncthreads();
    int o = 0;
    for (int i = threadIdx.x; i < 2048; i += 256)
        o |= ei[2 * i + 1];
    if (o) atomicOr(&s_or, 1);
    __syncthreads();
    if (threadIdx.x == 0) g_is64 = (s_or == 0) ? 1 : 0;
}

__device__ __forceinline__ int load_src(const int* ei, int E, int i, int is64)
{
    return is64 ? ei[2 * i] : ei[i];
}
__device__ __forceinline__ int load_dst(const int* ei, int E, int i, int is64)
{
    return is64 ? ei[2 * E + 2 * i] : ei[E + i];
}

// ---------------------------------------------------------------------------
// CSR build (by destination). Only integer atomics.
// ---------------------------------------------------------------------------
__global__ __launch_bounds__(256)
void zero_cnt_kernel(int n)
{
    int i = blockIdx.x * blockDim.x + threadIdx.x;
    if (i < n) g_cnt[i] = 0;
}

__global__ __launch_bounds__(256)
void hist_kernel(const int* __restrict__ ei, int E)
{
    int i = blockIdx.x * blockDim.x + threadIdx.x;
    int is64 = g_is64;
    if (i < E) atomicAdd(&g_cnt[load_dst(ei, E, i, is64)], 1);
}

__device__ __forceinline__ int block_exscan256(int v, int* sh)
{
    const int t = threadIdx.x;
    sh[t] = v;
    __syncthreads();
#pragma unroll
    for (int off = 1; off < 256; off <<= 1) {
        int u = (t >= off) ? sh[t - off] : 0;
        __syncthreads();
        sh[t] += u;
        __syncthreads();
    }
    return sh[t] - v;
}

__global__ __launch_bounds__(256)
void scan_partial(int n)
{
    __shared__ int sh[256];
    const int t = threadIdx.x;
    const int base = blockIdx.x * SCAN_CHUNK + t * 4;
    int s = 0;
#pragma unroll
    for (int j = 0; j < 4; j++)
        if (base + j < n) s += g_cnt[base + j];
    sh[t] = s;
    __syncthreads();
    for (int off = 128; off; off >>= 1) {
        if (t < off) sh[t] += sh[t + off];
        __syncthreads();
    }
    if (t == 0) g_bsums[blockIdx.x] = sh[0];
}

__global__ __launch_bounds__(256)
void scan_bsums(int nb)
{
    __shared__ int sh[256];
    const int t = threadIdx.x;
    int v = (t < nb) ? g_bsums[t] : 0;
    int ex = block_exscan256(v, sh);
    if (t < nb) g_boff[t] = ex;
}

__global__ __launch_bounds__(256)
void scan_final(int n, int E)
{
    __shared__ int sh[256];
    const int t = threadIdx.x;
    const int base = blockIdx.x * SCAN_CHUNK + t * 4;
    int c[4];
    int s = 0;
#pragma unroll
    for (int j = 0; j < 4; j++) {
        c[j] = (base + j < n) ? g_cnt[base + j] : 0;
        s += c[j];
    }
    int ex = block_exscan256(s, sh) + g_boff[blockIdx.x];
#pragma unroll
    for (int j = 0; j < 4; j++) {
        if (base + j < n) {
            g_off[base + j] = ex;
            g_cur[base + j] = ex;
        }
        ex += c[j];
    }
    if (blockIdx.x == 0 && t == 0) g_off[n] = E;
}

__global__ __launch_bounds__(256)
void scatter_kernel(const int* __restrict__ ei, int E)
{
    int i = blockIdx.x * blockDim.x + threadIdx.x;
    if (i >= E) return;
    int is64 = g_is64;
    int d = load_dst(ei, E, i, is64);
    int s = load_src(ei, E, i, is64);
    int pos = atomicAdd(&g_cur[d], 1);
    g_srcs[pos] = s;
}

// ---------------------------------------------------------------------------
// Fused GEMM + attention-logit epilogue. xp stored as fp16 (gather payload);
// logits computed from fp32 accumulators.
// ---------------------------------------------------------------------------
template<int K, bool FIRST>
__global__ __launch_bounds__(256)
void gemm_al_kernel(const float* __restrict__ Xin,
                    const float* __restrict__ W,
                    const float* __restrict__ att_s,
                    const float* __restrict__ att_d,
                    int n)
{
    const float* __restrict__ X = FIRST ? Xin : g_h;

    __shared__ __align__(16) float sW[64 * 64];
    __shared__ __align__(16) float sXT[64][132];

    const int tid = threadIdx.x;
    const int cx  = tid & 15;
    const int ry  = tid >> 4;
    const int row0 = blockIdx.x * 128;

    float C[8][4];
#pragma unroll
    for (int i = 0; i < 8; i++)
#pragma unroll
        for (int j = 0; j < 4; j++) C[i][j] = 0.f;

    for (int kc = 0; kc < K; kc += 64) {
        __syncthreads();
#pragma unroll
        for (int q = 0; q < 4; q++) {
            int idx4 = tid + q * 256;
            float4 v = *(const float4*)&W[kc * 64 + idx4 * 4];
            *(float4*)&sW[idx4 * 4] = v;
        }
#pragma unroll
        for (int q = 0; q < 8; q++) {
            int lin = tid + q * 256;
            int r  = lin >> 4;
            int c4 = lin & 15;
            int gr = row0 + r; if (gr > n - 1) gr = n - 1;
            float4 v = *(const float4*)&X[(long long)gr * K + kc + c4 * 4];
            sXT[c4 * 4 + 0][r] = v.x;
            sXT[c4 * 4 + 1][r] = v.y;
            sXT[c4 * 4 + 2][r] = v.z;
            sXT[c4 * 4 + 3][r] = v.w;
        }
        __syncthreads();
#pragma unroll
        for (int k = 0; k < 64; k++) {
            float4 wv = *(const float4*)&sW[k * 64 + cx * 4];
            float4 xa = *(const float4*)&sXT[k][ry * 8];
            float4 xb = *(const float4*)&sXT[k][ry * 8 + 4];
            float xr[8] = {xa.x, xa.y, xa.z, xa.w, xb.x, xb.y, xb.z, xb.w};
#pragma unroll
            for (int i = 0; i < 8; i++) {
                C[i][0] = fmaf(xr[i], wv.x, C[i][0]);
                C[i][1] = fmaf(xr[i], wv.y, C[i][1]);
                C[i][2] = fmaf(xr[i], wv.z, C[i][2]);
                C[i][3] = fmaf(xr[i], wv.w, C[i][3]);
            }
        }
    }

    const int h    = cx >> 3;
    const int lane = tid & 31;
    float asv[4], adv[4];
#pragma unroll
    for (int j = 0; j < 4; j++) {
        asv[j] = __ldg(&att_s[cx * 4 + j]);
        adv[j] = __ldg(&att_d[cx * 4 + j]);
    }

#pragma unroll
    for (int i = 0; i < 8; i++) {
        float als = 0.f, ald = 0.f;
#pragma unroll
        for (int j = 0; j < 4; j++) {
            als = fmaf(C[i][j], asv[j], als);
            ald = fmaf(C[i][j], adv[j], ald);
        }
#pragma unroll
        for (int off = 4; off; off >>= 1) {
            als += __shfl_down_sync(0xffffffffu, als, off, 8);
            ald += __shfl_down_sync(0xffffffffu, ald, off, 8);
        }
        int row = row0 + ry * 8 + i;
        if (row < n) {
            if ((lane & 7) == 0) {
                g_als[row * 2 + h] = als;
                g_ald[row * 2 + h] = ald;
            }
            __half2 p0 = __floats2half2_rn(C[i][0], C[i][1]);
            __half2 p1 = __floats2half2_rn(C[i][2], C[i][3]);
            __half2* dst = reinterpret_cast<__half2*>(&g_xp[row * HID + cx * 4]);
            dst[0] = p0;
            dst[1] = p1;
        }
    }
}

// ---------------------------------------------------------------------------
// Gather pass: one warp per destination node, half-warp per head.
// fp16 payload loads (half the L2 traffic), fp32 accumulation.
// ---------------------------------------------------------------------------
template<bool LAST>
__global__ __launch_bounds__(256)
void gather_kernel(const float* __restrict__ bias,
                   float* __restrict__ out, int n)
{
    int warp = (blockIdx.x * 256 + threadIdx.x) >> 5;
    int lane = threadIdx.x & 31;
    if (warp >= n) return;
    const int node = warp;
    const int h  = lane >> 4;           // half-warp = head
    const int hl = lane & 15;           // lane within half

    const float ald_h = __ldg(&g_ald[node * 2 + h]);

    // self loop
    float t0 = __ldg(&g_als[node * 2 + h]) + ald_h;
    t0 = fmaxf(t0, 0.2f * t0);
    float wself = __expf(t0);
    float2 xv = __half22float2(
        *reinterpret_cast<const __half2*>(&g_xp[node * HID + lane * 2]));
    float a0 = xv.x * wself, a1 = xv.y * wself;
    float segl = 0.f;

    const int beg = g_off[node];
    const int end = g_off[node + 1];
    for (int i = beg; i < end; i += 16) {
        int idx = i + hl;
        bool valid = idx < end;
        int sidx = valid ? __ldg(&g_srcs[idx]) : 0;
        float al = __ldg(&g_als[sidx * 2 + h]);
        float tt = al + ald_h;
        tt = fmaxf(tt, 0.2f * tt);
        float w = valid ? __expf(tt) : 0.f;
        segl += w;

        int cnt = min(16, end - i);
#pragma unroll 4
        for (int j = 0; j < cnt; j++) {
            float ww = __shfl_sync(0xffffffffu, w, j, 16);
            int   s  = __shfl_sync(0xffffffffu, sidx, j, 16);
            float2 xs = __half22float2(
                *reinterpret_cast<const __half2*>(&g_xp[s * HID + lane * 2]));
            a0 = fmaf(xs.x, ww, a0);
            a1 = fmaf(xs.y, ww, a1);
        }
    }

#pragma unroll
    for (int off = 8; off; off >>= 1)
        segl += __shfl_xor_sync(0xffffffffu, segl, off, 16);
    float seg = segl + wself;

    float inv = 1.f / (seg + 1e-16f);
    float2 bv = *(const float2*)&bias[lane * 2];
    float v0 = a0 * inv + bv.x;
    float v1 = a1 * inv + bv.y;
    if (!LAST) {
        v0 = v0 > 0.f ? v0 : expm1f(v0);
        v1 = v1 > 0.f ? v1 : expm1f(v1);
        *(float2*)&g_h[node * HID + lane * 2] = make_float2(v0, v1);
    } else {
        *(float2*)&out[node * HID + lane * 2] = make_float2(v0, v1);
    }
}

extern "C" void kernel_launch(void* const* d_in, const int* in_sizes, int n_in,
                              void* d_out, int out_size)
{
    const float* x   = (const float*)d_in[0];
    const int*   ei  = (const int*)d_in[1];
    const float* W1  = (const float*)d_in[2];
    const float* as1 = (const float*)d_in[3];
    const float* ad1 = (const float*)d_in[4];
    const float* b1  = (const float*)d_in[5];
    const float* W2  = (const float*)d_in[6];
    const float* as2 = (const float*)d_in[7];
    const float* ad2 = (const float*)d_in[8];
    const float* b2  = (const float*)d_in[9];

    const int n = in_sizes[0] / 128;          // 100000
    const int E = in_sizes[1] / 2;            // 1600000
    const int gb  = (n + 127) / 128;
    const int nbl = (n + 255) / 256;
    const int ebl = (E + 255) / 256;
    const int wbl = ((n * 32) + 255) / 256;
    const int sb  = (n + SCAN_CHUNK - 1) / SCAN_CHUNK;

    static cudaStream_t sCsr = nullptr, sMain = nullptr;
    static cudaEvent_t evFork = nullptr, evCsr = nullptr, evDone = nullptr;
    if (!sCsr) {
        cudaStreamCreateWithFlags(&sCsr,  cudaStreamNonBlocking);
        cudaStreamCreateWithFlags(&sMain, cudaStreamNonBlocking);
        cudaEventCreateWithFlags(&evFork, cudaEventDisableTiming);
        cudaEventCreateWithFlags(&evCsr,  cudaEventDisableTiming);
        cudaEventCreateWithFlags(&evDone, cudaEventDisableTiming);
    }

    cudaEventRecord(evFork, 0);
    cudaStreamWaitEvent(sCsr,  evFork, 0);
    cudaStreamWaitEvent(sMain, evFork, 0);

    detect_kernel<<<1, 256, 0, sCsr>>>(ei);
    zero_cnt_kernel<<<nbl, 256, 0, sCsr>>>(n);
    hist_kernel<<<ebl, 256, 0, sCsr>>>(ei, E);
    gemm_al_kernel<128, true><<<gb, 256, 0, sMain>>>(x, W1, as1, ad1, n);
    scan_partial<<<sb, 256, 0, sCsr>>>(n);
    scan_bsums<<<1, 256, 0, sCsr>>>(sb);
    scan_final<<<sb, 256, 0, sCsr>>>(n, E);
    scatter_kernel<<<ebl, 256, 0, sCsr>>>(ei, E);
    cudaEventRecord(evCsr, sCsr);

    cudaStreamWaitEvent(sMain, evCsr, 0);
    gather_kernel<false><<<wbl, 256, 0, sMain>>>(b1, nullptr, n);
    gemm_al_kernel<64, false><<<gb, 256, 0, sMain>>>(x, W2, as2, ad2, n);
    gather_kernel<true><<<wbl, 256, 0, sMain>>>(b2, (float*)d_out, n);

    cudaEventRecord(evDone, sMain);
    cudaStreamWaitEvent(0, evDone, 0);
}

// round 11
// speedup vs baseline: 1.3508x; 1.0573x over previous
#include <cuda_runtime.h>
#include <cuda_fp16.h>

#define NMAX 100000
#define EMAX 1600000
#define HID 64
#define SCAN_CHUNK 1024   // elements per scan block (256 thr * 4)

// scratch (no cudaMalloc allowed)
__device__ __align__(16) __half g_xp [NMAX * HID];   // fp16 message payload
__device__ __align__(16) float  g_h  [NMAX * HID];
__device__ float g_als[NMAX * 2];
__device__ float g_ald[NMAX * 2];
__device__ int   g_cnt[NMAX];
__device__ int   g_off[NMAX + 1];
__device__ int   g_cur[NMAX];
__device__ int   g_srcs[EMAX];
__device__ int   g_bsums[(NMAX + SCAN_CHUNK - 1) / SCAN_CHUNK];
__device__ int   g_boff [(NMAX + SCAN_CHUNK - 1) / SCAN_CHUNK];
__device__ int   g_is64;

// ---------------------------------------------------------------------------
// Detect whether edge_index is stored as int64 (high words zero) or int32.
// ---------------------------------------------------------------------------
__global__ __launch_bounds__(256)
void detect_kernel(const int* __restrict__ ei)
{
    __shared__ int s_or;
    if (threadIdx.x == 0) s_or = 0;
    __syncthreads();
    int o = 0;
    for (int i = threadIdx.x; i < 2048; i += 256)
        o |= ei[2 * i + 1];
    if (o) atomicOr(&s_or, 1);
    __syncthreads();
    if (threadIdx.x == 0) g_is64 = (s_or == 0) ? 1 : 0;
}

__device__ __forceinline__ int load_src(const int* ei, int E, int i, int is64)
{
    return is64 ? ei[2 * i] : ei[i];
}
__device__ __forceinline__ int load_dst(const int* ei, int E, int i, int is64)
{
    return is64 ? ei[2 * E + 2 * i] : ei[E + i];
}

// ---------------------------------------------------------------------------
// CSR build (by destination). Only integer atomics.
// ---------------------------------------------------------------------------
__global__ __launch_bounds__(256)
void zero_cnt_kernel(int n)
{
    int i = blockIdx.x * blockDim.x + threadIdx.x;
    if (i < n) g_cnt[i] = 0;
}

__global__ __launch_bounds__(256)
void hist_kernel(const int* __restrict__ ei, int E)
{
    int i = blockIdx.x * blockDim.x + threadIdx.x;
    int is64 = g_is64;
    if (i < E) atomicAdd(&g_cnt[load_dst(ei, E, i, is64)], 1);
}

__device__ __forceinline__ int block_exscan256(int v, int* sh)
{
    const int t = threadIdx.x;
    sh[t] = v;
    __syncthreads();
#pragma unroll
    for (int off = 1; off < 256; off <<= 1) {
        int u = (t >= off) ? sh[t - off] : 0;
        __syncthreads();
        sh[t] += u;
        __syncthreads();
    }
    return sh[t] - v;
}

__global__ __launch_bounds__(256)
void scan_partial(int n)
{
    __shared__ int sh[256];
    const int t = threadIdx.x;
    const int base = blockIdx.x * SCAN_CHUNK + t * 4;
    int s = 0;
#pragma unroll
    for (int j = 0; j < 4; j++)
        if (base + j < n) s += g_cnt[base + j];
    sh[t] = s;
    __syncthreads();
    for (int off = 128; off; off >>= 1) {
        if (t < off) sh[t] += sh[t + off];
        __syncthreads();
    }
    if (t == 0) g_bsums[blockIdx.x] = sh[0];
}

__global__ __launch_bounds__(256)
void scan_bsums(int nb)
{
    __shared__ int sh[256];
    const int t = threadIdx.x;
    int v = (t < nb) ? g_bsums[t] : 0;
    int ex = block_exscan256(v, sh);
    if (t < nb) g_boff[t] = ex;
}

__global__ __launch_bounds__(256)
void scan_final(int n, int E)
{
    __shared__ int sh[256];
    const int t = threadIdx.x;
    const int base = blockIdx.x * SCAN_CHUNK + t * 4;
    int c[4];
    int s = 0;
#pragma unroll
    for (int j = 0; j < 4; j++) {
        c[j] = (base + j < n) ? g_cnt[base + j] : 0;
        s += c[j];
    }
    int ex = block_exscan256(s, sh) + g_boff[blockIdx.x];
#pragma unroll
    for (int j = 0; j < 4; j++) {
        if (base + j < n) {
            g_off[base + j] = ex;
            g_cur[base + j] = ex;
        }
        ex += c[j];
    }
    if (blockIdx.x == 0 && t == 0) g_off[n] = E;
}

__global__ __launch_bounds__(256)
void scatter_kernel(const int* __restrict__ ei, int E)
{
    int i = blockIdx.x * blockDim.x + threadIdx.x;
    if (i >= E) return;
    int is64 = g_is64;
    int d = load_dst(ei, E, i, is64);
    int s = load_src(ei, E, i, is64);
    int pos = atomicAdd(&g_cur[d], 1);
    g_srcs[pos] = s;
}

// ---------------------------------------------------------------------------
// Fused GEMM + attention-logit epilogue. xp stored as fp16 (gather payload);
// logits computed from fp32 accumulators.
// ---------------------------------------------------------------------------
template<int K, bool FIRST>
__global__ __launch_bounds__(256)
void gemm_al_kernel(const float* __restrict__ Xin,
                    const float* __restrict__ W,
                    const float* __restrict__ att_s,
                    const float* __restrict__ att_d,
                    int n)
{
    const float* __restrict__ X = FIRST ? Xin : g_h;

    __shared__ __align__(16) float sW[64 * 64];
    __shared__ __align__(16) float sXT[64][132];

    const int tid = threadIdx.x;
    const int cx  = tid & 15;
    const int ry  = tid >> 4;
    const int row0 = blockIdx.x * 128;

    float C[8][4];
#pragma unroll
    for (int i = 0; i < 8; i++)
#pragma unroll
        for (int j = 0; j < 4; j++) C[i][j] = 0.f;

    for (int kc = 0; kc < K; kc += 64) {
        __syncthreads();
#pragma unroll
        for (int q = 0; q < 4; q++) {
            int idx4 = tid + q * 256;
            float4 v = *(const float4*)&W[kc * 64 + idx4 * 4];
            *(float4*)&sW[idx4 * 4] = v;
        }
#pragma unroll
        for (int q = 0; q < 8; q++) {
            int lin = tid + q * 256;
            int r  = lin >> 4;
            int c4 = lin & 15;
            int gr = row0 + r; if (gr > n - 1) gr = n - 1;
            float4 v = *(const float4*)&X[(long long)gr * K + kc + c4 * 4];
            sXT[c4 * 4 + 0][r] = v.x;
            sXT[c4 * 4 + 1][r] = v.y;
            sXT[c4 * 4 + 2][r] = v.z;
            sXT[c4 * 4 + 3][r] = v.w;
        }
        __syncthreads();
#pragma unroll
        for (int k = 0; k < 64; k++) {
            float4 wv = *(const float4*)&sW[k * 64 + cx * 4];
            float4 xa = *(const float4*)&sXT[k][ry * 8];
            float4 xb = *(const float4*)&sXT[k][ry * 8 + 4];
            float xr[8] = {xa.x, xa.y, xa.z, xa.w, xb.x, xb.y, xb.z, xb.w};
#pragma unroll
            for (int i = 0; i < 8; i++) {
                C[i][0] = fmaf(xr[i], wv.x, C[i][0]);
                C[i][1] = fmaf(xr[i], wv.y, C[i][1]);
                C[i][2] = fmaf(xr[i], wv.z, C[i][2]);
                C[i][3] = fmaf(xr[i], wv.w, C[i][3]);
            }
        }
    }

    const int h    = cx >> 3;
    const int lane = tid & 31;
    float asv[4], adv[4];
#pragma unroll
    for (int j = 0; j < 4; j++) {
        asv[j] = __ldg(&att_s[cx * 4 + j]);
        adv[j] = __ldg(&att_d[cx * 4 + j]);
    }

#pragma unroll
    for (int i = 0; i < 8; i++) {
        float als = 0.f, ald = 0.f;
#pragma unroll
        for (int j = 0; j < 4; j++) {
            als = fmaf(C[i][j], asv[j], als);
            ald = fmaf(C[i][j], adv[j], ald);
        }
#pragma unroll
        for (int off = 4; off; off >>= 1) {
            als += __shfl_down_sync(0xffffffffu, als, off, 8);
            ald += __shfl_down_sync(0xffffffffu, ald, off, 8);
        }
        int row = row0 + ry * 8 + i;
        if (row < n) {
            if ((lane & 7) == 0) {
                g_als[row * 2 + h] = als;
                g_ald[row * 2 + h] = ald;
            }
            __half2 p0 = __floats2half2_rn(C[i][0], C[i][1]);
            __half2 p1 = __floats2half2_rn(C[i][2], C[i][3]);
            __half2* dst = reinterpret_cast<__half2*>(&g_xp[row * HID + cx * 4]);
            dst[0] = p0;
            dst[1] = p1;
        }
    }
}

// ---------------------------------------------------------------------------
// Gather pass v3: one warp per destination node, half-warp per head.
// Branch-free 16-edge blocks; inner work split into two 8-edge sub-batches,
// each phase-split (8 independent LDG.64s in flight, then 16 FMAs) -> MLP=8.
// ---------------------------------------------------------------------------
template<bool LAST>
__global__ __launch_bounds__(256)
void gather_kernel(const float* __restrict__ bias,
                   float* __restrict__ out, int n)
{
    int warp = (blockIdx.x * 256 + threadIdx.x) >> 5;
    int lane = threadIdx.x & 31;
    if (warp >= n) return;
    const int node = warp;
    const int h  = lane >> 4;           // half-warp = head
    const int hl = lane & 15;           // lane within half

    const __half2* __restrict__ xp2 =
        reinterpret_cast<const __half2*>(g_xp) + lane;  // + 32*s per row

    const float ald_h = __ldg(&g_ald[node * 2 + h]);

    // self loop
    float t0 = __ldg(&g_als[node * 2 + h]) + ald_h;
    t0 = fmaxf(t0, 0.2f * t0);
    float wself = __expf(t0);
    float2 xv = __half22float2(xp2[node * 32]);
    float a0 = xv.x * wself, a1 = xv.y * wself;
    float segl = 0.f;

    const int beg = g_off[node];
    const int end = g_off[node + 1];
    for (int i = beg; i < end; i += 16) {
        int idx = i + hl;
        bool valid = idx < end;
        int sidx = valid ? __ldg(&g_srcs[idx]) : 0;
        float al = __ldg(&g_als[sidx * 2 + h]);
        float tt = al + ald_h;
        tt = fmaxf(tt, 0.2f * tt);
        float w = valid ? __expf(tt) : 0.f;
        segl += w;

#pragma unroll
        for (int jb = 0; jb < 16; jb += 8) {
            float  ww[8];
            float2 xs[8];
#pragma unroll
            for (int j = 0; j < 8; j++) {
                ww[j]  = __shfl_sync(0xffffffffu, w,    jb + j, 16);
                int s  = __shfl_sync(0xffffffffu, sidx, jb + j, 16);
                xs[j]  = __half22float2(xp2[s * 32]);
            }
#pragma unroll
            for (int j = 0; j < 8; j++) {
                a0 = fmaf(xs[j].x, ww[j], a0);
                a1 = fmaf(xs[j].y, ww[j], a1);
            }
        }
    }

#pragma unroll
    for (int off = 8; off; off >>= 1)
        segl += __shfl_xor_sync(0xffffffffu, segl, off, 16);
    float seg = segl + wself;

    float inv = 1.f / (seg + 1e-16f);
    float2 bv = *(const float2*)&bias[lane * 2];
    float v0 = a0 * inv + bv.x;
    float v1 = a1 * inv + bv.y;
    if (!LAST) {
        v0 = v0 > 0.f ? v0 : expm1f(v0);
        v1 = v1 > 0.f ? v1 : expm1f(v1);
        *(float2*)&g_h[node * HID + lane * 2] = make_float2(v0, v1);
    } else {
        *(float2*)&out[node * HID + lane * 2] = make_float2(v0, v1);
    }
}

extern "C" void kernel_launch(void* const* d_in, const int* in_sizes, int n_in,
                              void* d_out, int out_size)
{
    const float* x   = (const float*)d_in[0];
    const int*   ei  = (const int*)d_in[1];
    const float* W1  = (const float*)d_in[2];
    const float* as1 = (const float*)d_in[3];
    const float* ad1 = (const float*)d_in[4];
    const float* b1  = (const float*)d_in[5];
    const float* W2  = (const float*)d_in[6];
    const float* as2 = (const float*)d_in[7];
    const float* ad2 = (const float*)d_in[8];
    const float* b2  = (const float*)d_in[9];

    const int n = in_sizes[0] / 128;          // 100000
    const int E = in_sizes[1] / 2;            // 1600000
    const int gb  = (n + 127) / 128;
    const int nbl = (n + 255) / 256;
    const int ebl = (E + 255) / 256;
    const int wbl = ((n * 32) + 255) / 256;
    const int sb  = (n + SCAN_CHUNK - 1) / SCAN_CHUNK;

    static cudaStream_t sCsr = nullptr, sMain = nullptr;
    static cudaEvent_t evFork = nullptr, evCsr = nullptr, evDone = nullptr;
    if (!sCsr) {
        cudaStreamCreateWithFlags(&sCsr,  cudaStreamNonBlocking);
        cudaStreamCreateWithFlags(&sMain, cudaStreamNonBlocking);
        cudaEventCreateWithFlags(&evFork, cudaEventDisableTiming);
        cudaEventCreateWithFlags(&evCsr,  cudaEventDisableTiming);
        cudaEventCreateWithFlags(&evDone, cudaEventDisableTiming);
    }

    cudaEventRecord(evFork, 0);
    cudaStreamWaitEvent(sCsr,  evFork, 0);
    cudaStreamWaitEvent(sMain, evFork, 0);

    detect_kernel<<<1, 256, 0, sCsr>>>(ei);
    zero_cnt_kernel<<<nbl, 256, 0, sCsr>>>(n);
    hist_kernel<<<ebl, 256, 0, sCsr>>>(ei, E);
    gemm_al_kernel<128, true><<<gb, 256, 0, sMain>>>(x, W1, as1, ad1, n);
    scan_partial<<<sb, 256, 0, sCsr>>>(n);
    scan_bsums<<<1, 256, 0, sCsr>>>(sb);
    scan_final<<<sb, 256, 0, sCsr>>>(n, E);
    scatter_kernel<<<ebl, 256, 0, sCsr>>>(ei, E);
    cudaEventRecord(evCsr, sCsr);

    cudaStreamWaitEvent(sMain, evCsr, 0);
    gather_kernel<false><<<wbl, 256, 0, sMain>>>(b1, nullptr, n);
    gemm_al_kernel<64, false><<<gb, 256, 0, sMain>>>(x, W2, as2, ad2, n);
    gather_kernel<true><<<wbl, 256, 0, sMain>>>(b2, (float*)d_out, n);

    cudaEventRecord(evDone, sMain);
    cudaStreamWaitEvent(0, evDone, 0);
}